// round 12
// baseline (speedup 1.0000x reference)
#include <cuda_runtime.h>
#include <cuda_fp16.h>
#include <cstdint>

#define HID 32
#define MAX_T 2000000
#define MAX_E 1000000
#define MAX_M 4000000
#define SCAN_E 2048          // elems per scan block (256 thr * 8)
#define MAX_NB 4096

// Scratch buffers.
__device__ float4 g_tri4[MAX_T];                 // (a,b,c)*dis_src, pad
__device__ uint4  g_hs4[(size_t)MAX_T * 4];      // relu(out1)*dis as fp16: 32 halves / node
__device__ float  g_q  [MAX_E];                  // ec/cnt pre-divided (bit-identical gather table)
__device__ int    g_deg [MAX_T];                 // zeroed by k_scanC each call
__device__ int    g_off [MAX_T + 1];             // CSR row offsets (exclusive) + sentinel
__device__ int    g_cursor[MAX_T];
__device__ int    g_csr [MAX_M];                 // src lists grouped by dst
__device__ int    g_bsum[MAX_NB];

__device__ __forceinline__ unsigned h2_to_u32(__half2 h) {
    return *reinterpret_cast<unsigned*>(&h);
}
__device__ __forceinline__ __half2 u32_to_h2(unsigned u) {
    return *reinterpret_cast<__half2*>(&u);
}
// f32x2 packed math helpers (sm_10x SIMD fp32; IEEE-identical to scalar FFMA).
__device__ __forceinline__ unsigned long long pack2(float lo, float hi) {
    unsigned long long r;
    asm("mov.b64 %0, {%1,%2};" : "=l"(r) : "f"(lo), "f"(hi));
    return r;
}
__device__ __forceinline__ void unpack2(unsigned long long v, float& lo, float& hi) {
    asm("mov.b64 {%0,%1}, %2;" : "=f"(lo), "=f"(hi) : "l"(v));
}
__device__ __forceinline__ void ffma2(unsigned long long& d, unsigned long long a,
                                      unsigned long long b) {
    asm("fma.rn.f32x2 %0, %1, %2, %3;" : "=l"(d) : "l"(a), "l"(b), "l"(d));
}

// Degree histogram + per-edge prep: q = ec/cnt (exact, same fp op as reference),
// and base edge-cost output.
__global__ void k_degree_prep(const int* __restrict__ ei,
                              const float* __restrict__ ec,
                              const float* __restrict__ cnt,
                              float* __restrict__ o_ec, int M, int E) {
    int e = blockIdx.x * blockDim.x + threadIdx.x;
    if (e < E) {
        float c = cnt[e], v = ec[e];
        g_q[e]  = v / c;
        o_ec[e] = (c > 0.f) ? 0.f : v;
    }
    if (e < M) atomicAdd(&g_deg[__ldg(&ei[M + e])], 1);
}

// Triplet message receive (3 gathers from pre-divided q); stage t' in d_out;
// premultiplied tri.
__global__ void k_node1(const float* __restrict__ t12, const float* __restrict__ t13,
                        const float* __restrict__ t23,
                        const int* __restrict__ c12, const int* __restrict__ c13,
                        const int* __restrict__ c23,
                        float* __restrict__ o_t12, float* __restrict__ o_t13,
                        float* __restrict__ o_t23, int T) {
    int i = blockIdx.x * blockDim.x + threadIdx.x;
    if (i >= T) return;
    float a = t12[i] + g_q[c12[i]];
    float b = t13[i] + g_q[c13[i]];
    float c = t23[i] + g_q[c23[i]];
    o_t12[i] = a; o_t13[i] = b; o_t23[i] = c;
    float dis = rsqrtf((float)g_deg[i] + 1.0f);
    g_tri4[i] = make_float4(a * dis, b * dis, c * dis, 0.f);
}

// ---- exclusive scan of g_deg -> g_off (3 kernels) ----
__global__ void k_scanA(int T) {
    __shared__ int sh[256];
    int b = blockIdx.x, tx = threadIdx.x;
    int base = b * SCAN_E + tx * 8;
    int s = 0;
#pragma unroll
    for (int k = 0; k < 8; k++) { int i = base + k; if (i < T) s += g_deg[i]; }
    sh[tx] = s; __syncthreads();
    for (int o = 128; o > 0; o >>= 1) { if (tx < o) sh[tx] += sh[tx + o]; __syncthreads(); }
    if (tx == 0) g_bsum[b] = sh[0];
}

__global__ void k_scanB(int nb, int T) {
    __shared__ int sh[1024];
    int tx = threadIdx.x;
    int c = (nb + 1023) >> 10;
    int s = 0;
    for (int k = 0; k < c; k++) { int i = tx * c + k; if (i < nb) s += g_bsum[i]; }
    sh[tx] = s; __syncthreads();
    for (int o = 1; o < 1024; o <<= 1) {
        int v = (tx >= o) ? sh[tx - o] : 0; __syncthreads();
        sh[tx] += v; __syncthreads();
    }
    if (tx == 1023) g_off[T] = sh[1023];       // sentinel: total edge count
    int excl = (tx == 0) ? 0 : sh[tx - 1];
    for (int k = 0; k < c; k++) {
        int i = tx * c + k;
        if (i < nb) { int v = g_bsum[i]; g_bsum[i] = excl; excl += v; }
    }
}

// Also zeroes g_deg after its last read (next replay's k_degree starts from 0).
__global__ void k_scanC(int T) {
    __shared__ int sh[256];
    int b = blockIdx.x, tx = threadIdx.x;
    int base = b * SCAN_E + tx * 8;
    int loc[8]; int s = 0;
#pragma unroll
    for (int k = 0; k < 8; k++) {
        int i = base + k;
        int d = (i < T) ? g_deg[i] : 0;
        loc[k] = s; s += d;
        if (i < T) g_deg[i] = 0;
    }
    sh[tx] = s; __syncthreads();
    for (int o = 1; o < 256; o <<= 1) {
        int v = (tx >= o) ? sh[tx - o] : 0; __syncthreads();
        sh[tx] += v; __syncthreads();
    }
    int toff = ((tx == 0) ? 0 : sh[tx - 1]) + g_bsum[b];
#pragma unroll
    for (int k = 0; k < 8; k++) {
        int i = base + k;
        if (i < T) { int o = toff + loc[k]; g_off[i] = o; g_cursor[i] = o; }
    }
}

// Fill CSR: src lists grouped by dst.
__global__ void k_csr(const int* __restrict__ ei, int M) {
    int e = blockIdx.x * blockDim.x + threadIdx.x;
    if (e >= M) return;
    int src = __ldg(&ei[e]);
    int dst = __ldg(&ei[M + e]);
    int pos = atomicAdd(&g_cursor[dst], 1);
    g_csr[pos] = src;
}

// Layer 1 (fused), QUAD per node: csr + tri4 loads are quad-broadcast (1
// wavefront per quad instead of 4); each lane computes 8 of 32 h outputs and
// writes its 16B slice (fully coalesced 64B/node).
__global__ void k_layer1(const float* __restrict__ W1, const float* __restrict__ b1, int T) {
    __shared__ float W1s[96];
    __shared__ float b1s[HID];
    int tx = threadIdx.x;
    if (tx < 96)  W1s[tx] = W1[tx];
    if (tx < HID) b1s[tx] = b1[tx];
    __syncthreads();
    int tid = blockIdx.x * blockDim.x + tx;
    int i = tid >> 2;
    if (i >= T) return;
    int l4 = tx & 3;

    int s = g_off[i];
    int d = g_off[i + 1] - s;
    float dis = rsqrtf((float)d + 1.0f);

    // All 4 lanes compute the identical sum (broadcast loads are free).
    float4 sum = g_tri4[i];                 // self loop (already *dis_i)
    for (int n = 0; n < d; n++) {
        float4 t = g_tri4[g_csr[s + n]];
        sum.x += t.x; sum.y += t.y; sum.z += t.z;
    }
    float va = dis * sum.x, vb = dis * sum.y, vc = dis * sum.z;

    // Lane l4 computes h[8*l4 .. 8*l4+8) and writes one 16B packed slice.
    int j0 = 8 * l4;
    float h[8];
#pragma unroll
    for (int r = 0; r < 8; r++) {
        int j = j0 + r;
        h[r] = fmaxf(va * W1s[j] + vb * W1s[32 + j] + vc * W1s[64 + j] + b1s[j], 0.f) * dis;
    }
    uint4 u;
    u.x = h2_to_u32(__floats2half2_rn(h[0], h[1]));
    u.y = h2_to_u32(__floats2half2_rn(h[2], h[3]));
    u.z = h2_to_u32(__floats2half2_rn(h[4], h[5]));
    u.w = h2_to_u32(__floats2half2_rn(h[6], h[7]));
    g_hs4[(size_t)i * 4 + l4] = u;
}

__device__ __forceinline__ void acc_u4(float* sum, uint4 u) {
    float2 f0 = __half22float2(u32_to_h2(u.x));
    float2 f1 = __half22float2(u32_to_h2(u.y));
    float2 f2 = __half22float2(u32_to_h2(u.z));
    float2 f3 = __half22float2(u32_to_h2(u.w));
    sum[0]+=f0.x; sum[1]+=f0.y; sum[2]+=f1.x; sum[3]+=f1.y;
    sum[4]+=f2.x; sum[5]+=f2.y; sum[6]+=f3.x; sum[7]+=f3.y;
}

// Layer 2 + head (fused), 4 lanes per dst node; fp16 gather, fp32 accum,
// W2 via shfl + f32x2 FMA, lane-split epilogue (lane r owns output r).
__global__ void k_layer2_final(const float* __restrict__ W2, const float* __restrict__ b2,
                               const float* __restrict__ Wout, const float* __restrict__ bout,
                               const int* __restrict__ c12, const int* __restrict__ c13,
                               const int* __restrict__ c23,
                               float* __restrict__ o_ec,
                               float* __restrict__ o_t12, float* __restrict__ o_t13,
                               float* __restrict__ o_t23, int T) {
    __shared__ ulonglong2 W2p[HID * 8];   // W2[k][j] pre-packed as f32x2 pairs
    __shared__ float  b2s[HID];
    __shared__ float  Wos[96];
    __shared__ float  bos[3];
    int tx = threadIdx.x;
    {   // tx -> k = tx/8, pair-chunk c = tx%8 (chunk = 4 consecutive j)
        int k = tx >> 3, c = tx & 7;
        float4 w = *(const float4*)(W2 + k * HID + 4 * c);
        W2p[tx] = make_ulonglong2(pack2(w.x, w.y), pack2(w.z, w.w));
    }
    if (tx < HID) b2s[tx] = b2[tx];
    if (tx < 96)  Wos[tx] = Wout[tx];
    if (tx < 3)   bos[tx] = bout[tx];
    __syncthreads();

    int tid = blockIdx.x * blockDim.x + tx;
    int i  = tid >> 2;
    if (i >= T) return;
    int l4 = tx & 3;                  // lane owns h components [8*l4, 8*l4+8)

    // Lane-split early loads: lane r (r<3) owns output channel r.
    const int*  cp = (l4 == 0) ? c12 : (l4 == 1) ? c13 : c23;
    float*      tp = (l4 == 0) ? o_t12 : (l4 == 1) ? o_t13 : o_t23;
    int cidx = 0; float tval = 0.f;
    if (l4 < 3) { cidx = cp[i]; tval = tp[i]; }     // latency hidden behind gather+matmul

    int s = g_off[i];
    int d = g_off[i + 1] - s;
    float dis = rsqrtf((float)d + 1.0f);

    float sum[8];
    {
        uint4 u = g_hs4[(size_t)i * 4 + l4];      // self loop (already *dis_i)
        float2 f0 = __half22float2(u32_to_h2(u.x));
        float2 f1 = __half22float2(u32_to_h2(u.y));
        float2 f2 = __half22float2(u32_to_h2(u.z));
        float2 f3 = __half22float2(u32_to_h2(u.w));
        sum[0]=f0.x; sum[1]=f0.y; sum[2]=f1.x; sum[3]=f1.y;
        sum[4]=f2.x; sum[5]=f2.y; sum[6]=f3.x; sum[7]=f3.y;
    }
    for (int n = 0; n < d; n++) {
        uint4 u = g_hs4[(size_t)g_csr[s + n] * 4 + l4];
        acc_u4(sum, u);
    }
    float vr[8];
#pragma unroll
    for (int r = 0; r < 8; r++) vr[r] = dis * sum[r];

    // acc (8 floats) as 4 packed f32x2
    unsigned long long a01 = pack2(b2s[8*l4+0], b2s[8*l4+1]);
    unsigned long long a23 = pack2(b2s[8*l4+2], b2s[8*l4+3]);
    unsigned long long a45 = pack2(b2s[8*l4+4], b2s[8*l4+5]);
    unsigned long long a67 = pack2(b2s[8*l4+6], b2s[8*l4+7]);
#pragma unroll
    for (int k = 0; k < HID; k++) {
        float vk = __shfl_sync(0xffffffffu, vr[k & 7], k >> 3, 4);
        unsigned long long vk2 = pack2(vk, vk);
        ulonglong2 wa = W2p[k * 8 + 2 * l4];
        ulonglong2 wb = W2p[k * 8 + 2 * l4 + 1];
        ffma2(a01, vk2, wa.x);
        ffma2(a23, vk2, wa.y);
        ffma2(a45, vk2, wb.x);
        ffma2(a67, vk2, wb.y);
    }
    float acc[8];
    unpack2(a01, acc[0], acc[1]);
    unpack2(a23, acc[2], acc[3]);
    unpack2(a45, acc[4], acc[5]);
    unpack2(a67, acc[6], acc[7]);

    float d0 = 0.f, d1 = 0.f, d2 = 0.f;
#pragma unroll
    for (int r = 0; r < 8; r++) {
        float hj = fmaxf(acc[r], 0.f);
        int j = 8 * l4 + r;
        d0 += hj * Wos[j * 3 + 0];
        d1 += hj * Wos[j * 3 + 1];
        d2 += hj * Wos[j * 3 + 2];
    }
#pragma unroll
    for (int o = 1; o < 4; o <<= 1) {          // bfly: ALL lanes get full sums
        d0 += __shfl_xor_sync(0xffffffffu, d0, o, 4);
        d1 += __shfl_xor_sync(0xffffffffu, d1, o, 4);
        d2 += __shfl_xor_sync(0xffffffffu, d2, o, 4);
    }
    if (l4 < 3) {                              // lane r writes output channel r
        float dv = (l4 == 0) ? d0 : (l4 == 1) ? d1 : d2;
        dv += bos[l4];
        tp[i] = tval - dv;
        atomicAdd(&o_ec[cidx], dv);
    }
}

extern "C" void kernel_launch(void* const* d_in, const int* in_sizes, int n_in,
                              void* d_out, int out_size) {
    const float* ec   = (const float*)d_in[0];
    const float* t12  = (const float*)d_in[1];
    const float* t13  = (const float*)d_in[2];
    const float* t23  = (const float*)d_in[3];
    const int*   c12  = (const int*)  d_in[4];
    const int*   c13  = (const int*)  d_in[5];
    const int*   c23  = (const int*)  d_in[6];
    const float* cnt  = (const float*)d_in[7];
    const int*   ei   = (const int*)  d_in[8];
    const float* W1   = (const float*)d_in[9];
    const float* b1   = (const float*)d_in[10];
    const float* W2   = (const float*)d_in[11];
    const float* b2   = (const float*)d_in[12];
    const float* Wout = (const float*)d_in[13];
    const float* bout = (const float*)d_in[14];

    int E = in_sizes[0];
    int T = in_sizes[1];
    int M = in_sizes[8] / 2;

    float* o     = (float*)d_out;
    float* o_ec  = o;
    float* o_t12 = o + E;
    float* o_t13 = o + E + (size_t)T;
    float* o_t23 = o + E + (size_t)2 * T;

    const int B = 256;
    int gT  = (T + B - 1) / B;
    int gM  = (M + B - 1) / B;
    int nb  = (T + SCAN_E - 1) / SCAN_E;       // scan blocks
    int gQ  = (int)(((size_t)T * 4 + B - 1) / B);

    k_degree_prep<<<gM, B>>>(ei, ec, cnt, o_ec, M, E);
    k_node1<<<gT, B>>>(t12, t13, t23, c12, c13, c23,
                       o_t12, o_t13, o_t23, T);
    k_scanA<<<nb, B>>>(T);
    k_scanB<<<1, 1024>>>(nb, T);
    k_scanC<<<nb, B>>>(T);
    k_csr<<<gM, B>>>(ei, M);
    k_layer1<<<gQ, B>>>(W1, b1, T);
    k_layer2_final<<<gQ, B>>>(W2, b2, Wout, bout, c12, c13, c23,
                              o_ec, o_t12, o_t13, o_t23, T);
}

// round 13
// speedup vs baseline: 1.0308x; 1.0308x over previous
#include <cuda_runtime.h>
#include <cuda_fp16.h>
#include <cstdint>

#define HID 32
#define MAX_T 2000000
#define MAX_E 1000000
#define MAX_M 4000000
#define SCAN_E 2048          // elems per scan block (256 thr * 8)
#define MAX_NB 4096

// Scratch buffers.
__device__ float4 g_tri4[MAX_T];                 // (a,b,c)*dis_src, pad
__device__ uint4  g_hs4[(size_t)MAX_T * 4];      // relu(out1)*dis as fp16: 32 halves / node
__device__ float  g_q  [MAX_E];                  // ec/cnt pre-divided (bit-identical gather table)
__device__ int    g_deg [MAX_T];                 // zeroed by k_scanC each call
__device__ int    g_off [MAX_T + 1];             // CSR row offsets (exclusive) + sentinel
__device__ int    g_cursor[MAX_T];
__device__ int    g_csr [MAX_M];                 // src lists grouped by dst
__device__ int    g_bsum[MAX_NB];

__device__ __forceinline__ unsigned h2_to_u32(__half2 h) {
    return *reinterpret_cast<unsigned*>(&h);
}
__device__ __forceinline__ __half2 u32_to_h2(unsigned u) {
    return *reinterpret_cast<__half2*>(&u);
}
// f32x2 packed math helpers (sm_10x SIMD fp32; IEEE-identical to scalar FFMA).
__device__ __forceinline__ unsigned long long pack2(float lo, float hi) {
    unsigned long long r;
    asm("mov.b64 %0, {%1,%2};" : "=l"(r) : "f"(lo), "f"(hi));
    return r;
}
__device__ __forceinline__ void unpack2(unsigned long long v, float& lo, float& hi) {
    asm("mov.b64 {%0,%1}, %2;" : "=f"(lo), "=f"(hi) : "l"(v));
}
__device__ __forceinline__ void ffma2(unsigned long long& d, unsigned long long a,
                                      unsigned long long b) {
    asm("fma.rn.f32x2 %0, %1, %2, %3;" : "=l"(d) : "l"(a), "l"(b), "l"(d));
}

// Degree histogram + per-edge prep: q = ec/cnt (exact, same fp op as reference),
// and base edge-cost output.
__global__ void k_degree_prep(const int* __restrict__ ei,
                              const float* __restrict__ ec,
                              const float* __restrict__ cnt,
                              float* __restrict__ o_ec, int M, int E) {
    int e = blockIdx.x * blockDim.x + threadIdx.x;
    if (e < E) {
        float c = cnt[e], v = ec[e];
        g_q[e]  = v / c;
        o_ec[e] = (c > 0.f) ? 0.f : v;
    }
    if (e < M) atomicAdd(&g_deg[__ldg(&ei[M + e])], 1);
}

// Triplet message receive (3 gathers from pre-divided q); stage t' in d_out;
// premultiplied tri.
__global__ void k_node1(const float* __restrict__ t12, const float* __restrict__ t13,
                        const float* __restrict__ t23,
                        const int* __restrict__ c12, const int* __restrict__ c13,
                        const int* __restrict__ c23,
                        float* __restrict__ o_t12, float* __restrict__ o_t13,
                        float* __restrict__ o_t23, int T) {
    int i = blockIdx.x * blockDim.x + threadIdx.x;
    if (i >= T) return;
    float a = t12[i] + g_q[c12[i]];
    float b = t13[i] + g_q[c13[i]];
    float c = t23[i] + g_q[c23[i]];
    o_t12[i] = a; o_t13[i] = b; o_t23[i] = c;
    float dis = rsqrtf((float)g_deg[i] + 1.0f);
    g_tri4[i] = make_float4(a * dis, b * dis, c * dis, 0.f);
}

// ---- exclusive scan of g_deg -> g_off (2 kernels) ----
__global__ void k_scanA(int T) {
    __shared__ int sh[256];
    int b = blockIdx.x, tx = threadIdx.x;
    int base = b * SCAN_E + tx * 8;
    int s = 0;
#pragma unroll
    for (int k = 0; k < 8; k++) { int i = base + k; if (i < T) s += g_deg[i]; }
    sh[tx] = s; __syncthreads();
    for (int o = 128; o > 0; o >>= 1) { if (tx < o) sh[tx] += sh[tx + o]; __syncthreads(); }
    if (tx == 0) g_bsum[b] = sh[0];
}

// Fused scanB+scanC: each block computes its own global prefix by summing
// g_bsum[0..b) (L2-resident, <=nb reads spread over 256 threads), then does
// the local scan, writes offsets/cursors, zeroes g_deg (next replay ready),
// and the last block writes the g_off[T] sentinel.
__global__ void k_scanC(int T, int nb) {
    __shared__ int sh[256];
    __shared__ int pref;
    int b = blockIdx.x, tx = threadIdx.x;

    // block-wide sum of g_bsum[0..b)
    int p = 0;
    for (int k = tx; k < b; k += 256) p += g_bsum[k];
    sh[tx] = p; __syncthreads();
    for (int o = 128; o > 0; o >>= 1) { if (tx < o) sh[tx] += sh[tx + o]; __syncthreads(); }
    if (tx == 0) pref = sh[0];
    __syncthreads();
    int block_pref = pref;
    __syncthreads();

    int base = b * SCAN_E + tx * 8;
    int loc[8]; int s = 0;
#pragma unroll
    for (int k = 0; k < 8; k++) {
        int i = base + k;
        int d = (i < T) ? g_deg[i] : 0;
        loc[k] = s; s += d;
        if (i < T) g_deg[i] = 0;
    }
    sh[tx] = s; __syncthreads();
    for (int o = 1; o < 256; o <<= 1) {
        int v = (tx >= o) ? sh[tx - o] : 0; __syncthreads();
        sh[tx] += v; __syncthreads();
    }
    int toff = ((tx == 0) ? 0 : sh[tx - 1]) + block_pref;
#pragma unroll
    for (int k = 0; k < 8; k++) {
        int i = base + k;
        if (i < T) { int o = toff + loc[k]; g_off[i] = o; g_cursor[i] = o; }
    }
    if (b == nb - 1 && tx == 255) g_off[T] = block_pref + sh[255];
}

// Fill CSR: src lists grouped by dst.
__global__ void k_csr(const int* __restrict__ ei, int M) {
    int e = blockIdx.x * blockDim.x + threadIdx.x;
    if (e >= M) return;
    int src = __ldg(&ei[e]);
    int dst = __ldg(&ei[M + e]);
    int pos = atomicAdd(&g_cursor[dst], 1);
    g_csr[pos] = src;
}

// Layer 1 (fused, 1 thread/node): gather+sum raw 3-dim messages, @W1+b1, relu,
// store h*dis as fp16.
__global__ void k_layer1(const float* __restrict__ W1, const float* __restrict__ b1, int T) {
    __shared__ float W1s[96];
    __shared__ float b1s[HID];
    int tx = threadIdx.x;
    if (tx < 96)  W1s[tx] = W1[tx];
    if (tx < HID) b1s[tx] = b1[tx];
    __syncthreads();
    int i = blockIdx.x * blockDim.x + tx;
    if (i >= T) return;

    int s = g_off[i];
    int d = g_off[i + 1] - s;
    float dis = rsqrtf((float)d + 1.0f);

    float4 sum = g_tri4[i];                 // self loop (already *dis_i)
    for (int n = 0; n < d; n++) {
        float4 t = g_tri4[g_csr[s + n]];
        sum.x += t.x; sum.y += t.y; sum.z += t.z;
    }
    float va = dis * sum.x, vb = dis * sum.y, vc = dis * sum.z;

    float h[HID];
#pragma unroll
    for (int j = 0; j < HID; j++)
        h[j] = fmaxf(va * W1s[j] + vb * W1s[32 + j] + vc * W1s[64 + j] + b1s[j], 0.f) * dis;

    uint4* ph = g_hs4 + (size_t)i * 4;
#pragma unroll
    for (int q = 0; q < 4; q++) {           // each uint4 packs 8 halves
        uint4 u;
        u.x = h2_to_u32(__floats2half2_rn(h[8*q+0], h[8*q+1]));
        u.y = h2_to_u32(__floats2half2_rn(h[8*q+2], h[8*q+3]));
        u.z = h2_to_u32(__floats2half2_rn(h[8*q+4], h[8*q+5]));
        u.w = h2_to_u32(__floats2half2_rn(h[8*q+6], h[8*q+7]));
        ph[q] = u;
    }
}

__device__ __forceinline__ void acc_u4(float* sum, uint4 u) {
    float2 f0 = __half22float2(u32_to_h2(u.x));
    float2 f1 = __half22float2(u32_to_h2(u.y));
    float2 f2 = __half22float2(u32_to_h2(u.z));
    float2 f3 = __half22float2(u32_to_h2(u.w));
    sum[0]+=f0.x; sum[1]+=f0.y; sum[2]+=f1.x; sum[3]+=f1.y;
    sum[4]+=f2.x; sum[5]+=f2.y; sum[6]+=f3.x; sum[7]+=f3.y;
}

// Layer 2 + head (fused), 4 lanes per dst node; fp16 gather, fp32 accum,
// W2 via shfl + f32x2 FMA, lane-split epilogue (lane r owns output r).
__global__ void k_layer2_final(const float* __restrict__ W2, const float* __restrict__ b2,
                               const float* __restrict__ Wout, const float* __restrict__ bout,
                               const int* __restrict__ c12, const int* __restrict__ c13,
                               const int* __restrict__ c23,
                               float* __restrict__ o_ec,
                               float* __restrict__ o_t12, float* __restrict__ o_t13,
                               float* __restrict__ o_t23, int T) {
    __shared__ ulonglong2 W2p[HID * 8];   // W2[k][j] pre-packed as f32x2 pairs
    __shared__ float  b2s[HID];
    __shared__ float  Wos[96];
    __shared__ float  bos[3];
    int tx = threadIdx.x;
    {   // tx -> k = tx/8, pair-chunk c = tx%8 (chunk = 4 consecutive j)
        int k = tx >> 3, c = tx & 7;
        float4 w = *(const float4*)(W2 + k * HID + 4 * c);
        W2p[tx] = make_ulonglong2(pack2(w.x, w.y), pack2(w.z, w.w));
    }
    if (tx < HID) b2s[tx] = b2[tx];
    if (tx < 96)  Wos[tx] = Wout[tx];
    if (tx < 3)   bos[tx] = bout[tx];
    __syncthreads();

    int tid = blockIdx.x * blockDim.x + tx;
    int i  = tid >> 2;
    if (i >= T) return;
    int l4 = tx & 3;                  // lane owns h components [8*l4, 8*l4+8)

    // Lane-split early loads: lane r (r<3) owns output channel r.
    const int*  cp = (l4 == 0) ? c12 : (l4 == 1) ? c13 : c23;
    float*      tp = (l4 == 0) ? o_t12 : (l4 == 1) ? o_t13 : o_t23;
    int cidx = 0; float tval = 0.f;
    if (l4 < 3) { cidx = cp[i]; tval = tp[i]; }     // latency hidden behind gather+matmul

    int s = g_off[i];
    int d = g_off[i + 1] - s;
    float dis = rsqrtf((float)d + 1.0f);

    float sum[8];
    {
        uint4 u = g_hs4[(size_t)i * 4 + l4];      // self loop (already *dis_i)
        float2 f0 = __half22float2(u32_to_h2(u.x));
        float2 f1 = __half22float2(u32_to_h2(u.y));
        float2 f2 = __half22float2(u32_to_h2(u.z));
        float2 f3 = __half22float2(u32_to_h2(u.w));
        sum[0]=f0.x; sum[1]=f0.y; sum[2]=f1.x; sum[3]=f1.y;
        sum[4]=f2.x; sum[5]=f2.y; sum[6]=f3.x; sum[7]=f3.y;
    }
    for (int n = 0; n < d; n++) {
        uint4 u = g_hs4[(size_t)g_csr[s + n] * 4 + l4];
        acc_u4(sum, u);
    }
    float vr[8];
#pragma unroll
    for (int r = 0; r < 8; r++) vr[r] = dis * sum[r];

    // acc (8 floats) as 4 packed f32x2
    unsigned long long a01 = pack2(b2s[8*l4+0], b2s[8*l4+1]);
    unsigned long long a23 = pack2(b2s[8*l4+2], b2s[8*l4+3]);
    unsigned long long a45 = pack2(b2s[8*l4+4], b2s[8*l4+5]);
    unsigned long long a67 = pack2(b2s[8*l4+6], b2s[8*l4+7]);
#pragma unroll
    for (int k = 0; k < HID; k++) {
        float vk = __shfl_sync(0xffffffffu, vr[k & 7], k >> 3, 4);
        unsigned long long vk2 = pack2(vk, vk);
        ulonglong2 wa = W2p[k * 8 + 2 * l4];
        ulonglong2 wb = W2p[k * 8 + 2 * l4 + 1];
        ffma2(a01, vk2, wa.x);
        ffma2(a23, vk2, wa.y);
        ffma2(a45, vk2, wb.x);
        ffma2(a67, vk2, wb.y);
    }
    float acc[8];
    unpack2(a01, acc[0], acc[1]);
    unpack2(a23, acc[2], acc[3]);
    unpack2(a45, acc[4], acc[5]);
    unpack2(a67, acc[6], acc[7]);

    float d0 = 0.f, d1 = 0.f, d2 = 0.f;
#pragma unroll
    for (int r = 0; r < 8; r++) {
        float hj = fmaxf(acc[r], 0.f);
        int j = 8 * l4 + r;
        d0 += hj * Wos[j * 3 + 0];
        d1 += hj * Wos[j * 3 + 1];
        d2 += hj * Wos[j * 3 + 2];
    }
#pragma unroll
    for (int o = 1; o < 4; o <<= 1) {          // bfly: ALL lanes get full sums
        d0 += __shfl_xor_sync(0xffffffffu, d0, o, 4);
        d1 += __shfl_xor_sync(0xffffffffu, d1, o, 4);
        d2 += __shfl_xor_sync(0xffffffffu, d2, o, 4);
    }
    if (l4 < 3) {                              // lane r writes output channel r
        float dv = (l4 == 0) ? d0 : (l4 == 1) ? d1 : d2;
        dv += bos[l4];
        tp[i] = tval - dv;
        atomicAdd(&o_ec[cidx], dv);
    }
}

extern "C" void kernel_launch(void* const* d_in, const int* in_sizes, int n_in,
                              void* d_out, int out_size) {
    const float* ec   = (const float*)d_in[0];
    const float* t12  = (const float*)d_in[1];
    const float* t13  = (const float*)d_in[2];
    const float* t23  = (const float*)d_in[3];
    const int*   c12  = (const int*)  d_in[4];
    const int*   c13  = (const int*)  d_in[5];
    const int*   c23  = (const int*)  d_in[6];
    const float* cnt  = (const float*)d_in[7];
    const int*   ei   = (const int*)  d_in[8];
    const float* W1   = (const float*)d_in[9];
    const float* b1   = (const float*)d_in[10];
    const float* W2   = (const float*)d_in[11];
    const float* b2   = (const float*)d_in[12];
    const float* Wout = (const float*)d_in[13];
    const float* bout = (const float*)d_in[14];

    int E = in_sizes[0];
    int T = in_sizes[1];
    int M = in_sizes[8] / 2;

    float* o     = (float*)d_out;
    float* o_ec  = o;
    float* o_t12 = o + E;
    float* o_t13 = o + E + (size_t)T;
    float* o_t23 = o + E + (size_t)2 * T;

    const int B = 256;
    int gT  = (T + B - 1) / B;
    int gM  = (M + B - 1) / B;
    int nb  = (T + SCAN_E - 1) / SCAN_E;       // scan blocks
    int gQ  = (int)(((size_t)T * 4 + B - 1) / B);

    k_degree_prep<<<gM, B>>>(ei, ec, cnt, o_ec, M, E);
    k_node1<<<gT, B>>>(t12, t13, t23, c12, c13, c23,
                       o_t12, o_t13, o_t23, T);
    k_scanA<<<nb, B>>>(T);
    k_scanC<<<nb, B>>>(T, nb);
    k_csr<<<gM, B>>>(ei, M);
    k_layer1<<<gT, B>>>(W1, b1, T);
    k_layer2_final<<<gQ, B>>>(W2, b2, Wout, bout, c12, c13, c23,
                              o_ec, o_t12, o_t13, o_t23, T);
}

// round 14
// speedup vs baseline: 1.0484x; 1.0170x over previous
#include <cuda_runtime.h>
#include <cuda_fp16.h>
#include <cstdint>

#define HID 32
#define MAX_T 2000000
#define MAX_E 1000000
#define MAX_M 4000000
#define SCAN_E 2048          // elems per scan block (256 thr * 8)
#define MAX_NB 4096

// Scratch buffers.
__device__ float4 g_tri4[MAX_T];                 // (a,b,c)*dis_src, pad
__device__ uint4  g_hs4[(size_t)MAX_T * 4];      // relu(out1)*dis as fp16: 32 halves / node
__device__ float  g_q  [MAX_E];                  // ec/cnt pre-divided (bit-identical gather table)
__device__ int    g_deg [MAX_T];                 // zeroed by k_scanC each call
__device__ int    g_off [MAX_T + 1];             // CSR row offsets (exclusive) + sentinel
__device__ int    g_cursor[MAX_T];
__device__ int    g_csr [MAX_M];                 // src lists grouped by dst
__device__ int    g_bsum[MAX_NB];

__device__ __forceinline__ unsigned h2_to_u32(__half2 h) {
    return *reinterpret_cast<unsigned*>(&h);
}
__device__ __forceinline__ __half2 u32_to_h2(unsigned u) {
    return *reinterpret_cast<__half2*>(&u);
}
// f32x2 packed math helpers (sm_10x SIMD fp32; IEEE-identical to scalar FFMA).
__device__ __forceinline__ unsigned long long pack2(float lo, float hi) {
    unsigned long long r;
    asm("mov.b64 %0, {%1,%2};" : "=l"(r) : "f"(lo), "f"(hi));
    return r;
}
__device__ __forceinline__ void unpack2(unsigned long long v, float& lo, float& hi) {
    asm("mov.b64 {%0,%1}, %2;" : "=f"(lo), "=f"(hi) : "l"(v));
}
__device__ __forceinline__ void ffma2(unsigned long long& d, unsigned long long a,
                                      unsigned long long b) {
    asm("fma.rn.f32x2 %0, %1, %2, %3;" : "=l"(d) : "l"(a), "l"(b), "l"(d));
}

// Degree histogram + per-edge prep: q = ec/cnt (exact, same fp op as reference),
// and base edge-cost output.
__global__ void k_degree_prep(const int* __restrict__ ei,
                              const float* __restrict__ ec,
                              const float* __restrict__ cnt,
                              float* __restrict__ o_ec, int M, int E) {
    int e = blockIdx.x * blockDim.x + threadIdx.x;
    if (e < E) {
        float c = cnt[e], v = ec[e];
        g_q[e]  = v / c;
        o_ec[e] = (c > 0.f) ? 0.f : v;
    }
    if (e < M) atomicAdd(&g_deg[__ldg(&ei[M + e])], 1);
}

// Triplet message receive (3 gathers from pre-divided q); stage t' in d_out;
// premultiplied tri.
__global__ void k_node1(const float* __restrict__ t12, const float* __restrict__ t13,
                        const float* __restrict__ t23,
                        const int* __restrict__ c12, const int* __restrict__ c13,
                        const int* __restrict__ c23,
                        float* __restrict__ o_t12, float* __restrict__ o_t13,
                        float* __restrict__ o_t23, int T) {
    int i = blockIdx.x * blockDim.x + threadIdx.x;
    if (i >= T) return;
    float a = t12[i] + g_q[c12[i]];
    float b = t13[i] + g_q[c13[i]];
    float c = t23[i] + g_q[c23[i]];
    o_t12[i] = a; o_t13[i] = b; o_t23[i] = c;
    float dis = rsqrtf((float)g_deg[i] + 1.0f);
    g_tri4[i] = make_float4(a * dis, b * dis, c * dis, 0.f);
}

// ---- exclusive scan of g_deg -> g_off (3 kernels) ----
__global__ void k_scanA(int T) {
    __shared__ int sh[256];
    int b = blockIdx.x, tx = threadIdx.x;
    int base = b * SCAN_E + tx * 8;
    int s = 0;
#pragma unroll
    for (int k = 0; k < 8; k++) { int i = base + k; if (i < T) s += g_deg[i]; }
    sh[tx] = s; __syncthreads();
    for (int o = 128; o > 0; o >>= 1) { if (tx < o) sh[tx] += sh[tx + o]; __syncthreads(); }
    if (tx == 0) g_bsum[b] = sh[0];
}

__global__ void k_scanB(int nb, int T) {
    __shared__ int sh[1024];
    int tx = threadIdx.x;
    int c = (nb + 1023) >> 10;
    int s = 0;
    for (int k = 0; k < c; k++) { int i = tx * c + k; if (i < nb) s += g_bsum[i]; }
    sh[tx] = s; __syncthreads();
    for (int o = 1; o < 1024; o <<= 1) {
        int v = (tx >= o) ? sh[tx - o] : 0; __syncthreads();
        sh[tx] += v; __syncthreads();
    }
    if (tx == 1023) g_off[T] = sh[1023];       // sentinel: total edge count
    int excl = (tx == 0) ? 0 : sh[tx - 1];
    for (int k = 0; k < c; k++) {
        int i = tx * c + k;
        if (i < nb) { int v = g_bsum[i]; g_bsum[i] = excl; excl += v; }
    }
}

// Also zeroes g_deg after its last read (next replay's k_degree starts from 0).
__global__ void k_scanC(int T) {
    __shared__ int sh[256];
    int b = blockIdx.x, tx = threadIdx.x;
    int base = b * SCAN_E + tx * 8;
    int loc[8]; int s = 0;
#pragma unroll
    for (int k = 0; k < 8; k++) {
        int i = base + k;
        int d = (i < T) ? g_deg[i] : 0;
        loc[k] = s; s += d;
        if (i < T) g_deg[i] = 0;
    }
    sh[tx] = s; __syncthreads();
    for (int o = 1; o < 256; o <<= 1) {
        int v = (tx >= o) ? sh[tx - o] : 0; __syncthreads();
        sh[tx] += v; __syncthreads();
    }
    int toff = ((tx == 0) ? 0 : sh[tx - 1]) + g_bsum[b];
#pragma unroll
    for (int k = 0; k < 8; k++) {
        int i = base + k;
        if (i < T) { int o = toff + loc[k]; g_off[i] = o; g_cursor[i] = o; }
    }
}

// Fill CSR: src lists grouped by dst.
__global__ void k_csr(const int* __restrict__ ei, int M) {
    int e = blockIdx.x * blockDim.x + threadIdx.x;
    if (e >= M) return;
    int src = __ldg(&ei[e]);
    int dst = __ldg(&ei[M + e]);
    int pos = atomicAdd(&g_cursor[dst], 1);
    g_csr[pos] = src;
}

// Layer 1 (fused, 1 thread/node): gather+sum raw 3-dim messages, @W1+b1, relu,
// store h*dis as fp16.
__global__ void k_layer1(const float* __restrict__ W1, const float* __restrict__ b1, int T) {
    __shared__ float W1s[96];
    __shared__ float b1s[HID];
    int tx = threadIdx.x;
    if (tx < 96)  W1s[tx] = W1[tx];
    if (tx < HID) b1s[tx] = b1[tx];
    __syncthreads();
    int i = blockIdx.x * blockDim.x + tx;
    if (i >= T) return;

    int s = g_off[i];
    int d = g_off[i + 1] - s;
    float dis = rsqrtf((float)d + 1.0f);

    float4 sum = g_tri4[i];                 // self loop (already *dis_i)
    for (int n = 0; n < d; n++) {
        float4 t = g_tri4[g_csr[s + n]];
        sum.x += t.x; sum.y += t.y; sum.z += t.z;
    }
    float va = dis * sum.x, vb = dis * sum.y, vc = dis * sum.z;

    float h[HID];
#pragma unroll
    for (int j = 0; j < HID; j++)
        h[j] = fmaxf(va * W1s[j] + vb * W1s[32 + j] + vc * W1s[64 + j] + b1s[j], 0.f) * dis;

    uint4* ph = g_hs4 + (size_t)i * 4;
#pragma unroll
    for (int q = 0; q < 4; q++) {           // each uint4 packs 8 halves
        uint4 u;
        u.x = h2_to_u32(__floats2half2_rn(h[8*q+0], h[8*q+1]));
        u.y = h2_to_u32(__floats2half2_rn(h[8*q+2], h[8*q+3]));
        u.z = h2_to_u32(__floats2half2_rn(h[8*q+4], h[8*q+5]));
        u.w = h2_to_u32(__floats2half2_rn(h[8*q+6], h[8*q+7]));
        ph[q] = u;
    }
}

__device__ __forceinline__ void acc_u4(float* sum, uint4 u) {
    float2 f0 = __half22float2(u32_to_h2(u.x));
    float2 f1 = __half22float2(u32_to_h2(u.y));
    float2 f2 = __half22float2(u32_to_h2(u.z));
    float2 f3 = __half22float2(u32_to_h2(u.w));
    sum[0]+=f0.x; sum[1]+=f0.y; sum[2]+=f1.x; sum[3]+=f1.y;
    sum[4]+=f2.x; sum[5]+=f2.y; sum[6]+=f3.x; sum[7]+=f3.y;
}

// Layer 2 + head (fused), 4 lanes per dst node; fp16 gather, fp32 accum,
// W2 via shfl + f32x2 FMA, lane-split epilogue (lane r owns output r).
__global__ void k_layer2_final(const float* __restrict__ W2, const float* __restrict__ b2,
                               const float* __restrict__ Wout, const float* __restrict__ bout,
                               const int* __restrict__ c12, const int* __restrict__ c13,
                               const int* __restrict__ c23,
                               float* __restrict__ o_ec,
                               float* __restrict__ o_t12, float* __restrict__ o_t13,
                               float* __restrict__ o_t23, int T) {
    __shared__ ulonglong2 W2p[HID * 8];   // W2[k][j] pre-packed as f32x2 pairs
    __shared__ float  b2s[HID];
    __shared__ float  Wos[96];
    __shared__ float  bos[3];
    int tx = threadIdx.x;
    {   // tx -> k = tx/8, pair-chunk c = tx%8 (chunk = 4 consecutive j)
        int k = tx >> 3, c = tx & 7;
        float4 w = *(const float4*)(W2 + k * HID + 4 * c);
        W2p[tx] = make_ulonglong2(pack2(w.x, w.y), pack2(w.z, w.w));
    }
    if (tx < HID) b2s[tx] = b2[tx];
    if (tx < 96)  Wos[tx] = Wout[tx];
    if (tx < 3)   bos[tx] = bout[tx];
    __syncthreads();

    int tid = blockIdx.x * blockDim.x + tx;
    int i  = tid >> 2;
    if (i >= T) return;
    int l4 = tx & 3;                  // lane owns h components [8*l4, 8*l4+8)

    // Lane-split early loads: lane r (r<3) owns output channel r.
    const int*  cp = (l4 == 0) ? c12 : (l4 == 1) ? c13 : c23;
    float*      tp = (l4 == 0) ? o_t12 : (l4 == 1) ? o_t13 : o_t23;
    int cidx = 0; float tval = 0.f;
    if (l4 < 3) { cidx = cp[i]; tval = tp[i]; }     // latency hidden behind gather+matmul

    int s = g_off[i];
    int d = g_off[i + 1] - s;
    float dis = rsqrtf((float)d + 1.0f);

    float sum[8];
    {
        uint4 u = g_hs4[(size_t)i * 4 + l4];      // self loop (already *dis_i)
        float2 f0 = __half22float2(u32_to_h2(u.x));
        float2 f1 = __half22float2(u32_to_h2(u.y));
        float2 f2 = __half22float2(u32_to_h2(u.z));
        float2 f3 = __half22float2(u32_to_h2(u.w));
        sum[0]=f0.x; sum[1]=f0.y; sum[2]=f1.x; sum[3]=f1.y;
        sum[4]=f2.x; sum[5]=f2.y; sum[6]=f3.x; sum[7]=f3.y;
    }
    for (int n = 0; n < d; n++) {
        uint4 u = g_hs4[(size_t)g_csr[s + n] * 4 + l4];
        acc_u4(sum, u);
    }
    float vr[8];
#pragma unroll
    for (int r = 0; r < 8; r++) vr[r] = dis * sum[r];

    // acc (8 floats) as 4 packed f32x2
    unsigned long long a01 = pack2(b2s[8*l4+0], b2s[8*l4+1]);
    unsigned long long a23 = pack2(b2s[8*l4+2], b2s[8*l4+3]);
    unsigned long long a45 = pack2(b2s[8*l4+4], b2s[8*l4+5]);
    unsigned long long a67 = pack2(b2s[8*l4+6], b2s[8*l4+7]);
#pragma unroll
    for (int k = 0; k < HID; k++) {
        float vk = __shfl_sync(0xffffffffu, vr[k & 7], k >> 3, 4);
        unsigned long long vk2 = pack2(vk, vk);
        ulonglong2 wa = W2p[k * 8 + 2 * l4];
        ulonglong2 wb = W2p[k * 8 + 2 * l4 + 1];
        ffma2(a01, vk2, wa.x);
        ffma2(a23, vk2, wa.y);
        ffma2(a45, vk2, wb.x);
        ffma2(a67, vk2, wb.y);
    }
    float acc[8];
    unpack2(a01, acc[0], acc[1]);
    unpack2(a23, acc[2], acc[3]);
    unpack2(a45, acc[4], acc[5]);
    unpack2(a67, acc[6], acc[7]);

    float d0 = 0.f, d1 = 0.f, d2 = 0.f;
#pragma unroll
    for (int r = 0; r < 8; r++) {
        float hj = fmaxf(acc[r], 0.f);
        int j = 8 * l4 + r;
        d0 += hj * Wos[j * 3 + 0];
        d1 += hj * Wos[j * 3 + 1];
        d2 += hj * Wos[j * 3 + 2];
    }
#pragma unroll
    for (int o = 1; o < 4; o <<= 1) {          // bfly: ALL lanes get full sums
        d0 += __shfl_xor_sync(0xffffffffu, d0, o, 4);
        d1 += __shfl_xor_sync(0xffffffffu, d1, o, 4);
        d2 += __shfl_xor_sync(0xffffffffu, d2, o, 4);
    }
    if (l4 < 3) {                              // lane r writes output channel r
        float dv = (l4 == 0) ? d0 : (l4 == 1) ? d1 : d2;
        dv += bos[l4];
        tp[i] = tval - dv;
        atomicAdd(&o_ec[cidx], dv);
    }
}

extern "C" void kernel_launch(void* const* d_in, const int* in_sizes, int n_in,
                              void* d_out, int out_size) {
    const float* ec   = (const float*)d_in[0];
    const float* t12  = (const float*)d_in[1];
    const float* t13  = (const float*)d_in[2];
    const float* t23  = (const float*)d_in[3];
    const int*   c12  = (const int*)  d_in[4];
    const int*   c13  = (const int*)  d_in[5];
    const int*   c23  = (const int*)  d_in[6];
    const float* cnt  = (const float*)d_in[7];
    const int*   ei   = (const int*)  d_in[8];
    const float* W1   = (const float*)d_in[9];
    const float* b1   = (const float*)d_in[10];
    const float* W2   = (const float*)d_in[11];
    const float* b2   = (const float*)d_in[12];
    const float* Wout = (const float*)d_in[13];
    const float* bout = (const float*)d_in[14];

    int E = in_sizes[0];
    int T = in_sizes[1];
    int M = in_sizes[8] / 2;

    float* o     = (float*)d_out;
    float* o_ec  = o;
    float* o_t12 = o + E;
    float* o_t13 = o + E + (size_t)T;
    float* o_t23 = o + E + (size_t)2 * T;

    const int B = 256;
    int gT  = (T + B - 1) / B;
    int gM  = (M + B - 1) / B;
    int nb  = (T + SCAN_E - 1) / SCAN_E;       // scan blocks
    int gQ  = (int)(((size_t)T * 4 + B - 1) / B);

    k_degree_prep<<<gM, B>>>(ei, ec, cnt, o_ec, M, E);
    k_node1<<<gT, B>>>(t12, t13, t23, c12, c13, c23,
                       o_t12, o_t13, o_t23, T);
    k_scanA<<<nb, B>>>(T);
    k_scanB<<<1, 1024>>>(nb, T);
    k_scanC<<<nb, B>>>(T);
    k_csr<<<gM, B>>>(ei, M);
    k_layer1<<<gT, B>>>(W1, b1, T);
    k_layer2_final<<<gQ, B>>>(W2, b2, Wout, bout, c12, c13, c23,
                              o_ec, o_t12, o_t13, o_t23, T);
}